// round 4
// baseline (speedup 1.0000x reference)
#include <cuda_runtime.h>
#include <cuda_fp16.h>
#include <cstdint>
#include <cstddef>

// ---------------------------------------------------------------------------
// Problem constants
// ---------------------------------------------------------------------------
#define B_DIM 4
#define S_DIM 2048
#define V_DIM 32000
#define K_DIM 512            // 2*D
#define D_DIM 256
#define M_DIM 8192           // B*S
#define LUT_N 4096

// exact-double constants rounded to f32
#define PHI_F   1.6180339887498949f          // (1+sqrt5)/2
#define CINV_F  651.8986469044033f           // 4096 / (2*pi)
#define GRID_F  0.0015339807878856412f       // (2*pi) / 4096

// GEMM tiling
#define TM 128
#define TN 256
#define KC 64                // k elements per stage = 128 bytes fp16
#define NKC 8                // 512 / 64

// scratch (device globals allowed; runtime alloc is not)
static __device__ __align__(256) float  g_sin[LUT_N];
static __device__ __align__(256) float  g_cos[LUT_N];
static __device__ __align__(256) __half g_A[(size_t)M_DIM * K_DIM];
static __device__ __align__(256) __half g_B[(size_t)V_DIM * K_DIM];

// ---------------------------------------------------------------------------
// PTX helpers (base-arch only: cp.async, ldmatrix, mma.sync)
// ---------------------------------------------------------------------------
__device__ __forceinline__ uint32_t smem_u32(const void* p) {
    return (uint32_t)__cvta_generic_to_shared(p);
}
__device__ __forceinline__ void cp_async16(uint32_t dst, const void* src) {
    asm volatile("cp.async.cg.shared.global [%0], [%1], 16;"
                 :: "r"(dst), "l"(src) : "memory");
}
#define CP_COMMIT() asm volatile("cp.async.commit_group;" ::: "memory")
#define CP_WAIT0()  asm volatile("cp.async.wait_group 0;" ::: "memory")

__device__ __forceinline__ void ldmatrix_x4(uint32_t* r, uint32_t addr) {
    asm volatile("ldmatrix.sync.aligned.m8n8.x4.shared.b16 {%0,%1,%2,%3}, [%4];"
                 : "=r"(r[0]), "=r"(r[1]), "=r"(r[2]), "=r"(r[3]) : "r"(addr));
}

__device__ __forceinline__ void mma16816(float* c, const uint32_t* a,
                                         uint32_t b0, uint32_t b1) {
    asm volatile(
        "mma.sync.aligned.m16n8k16.row.col.f32.f16.f16.f32 "
        "{%0,%1,%2,%3}, {%4,%5,%6,%7}, {%8,%9}, {%0,%1,%2,%3};"
        : "+f"(c[0]), "+f"(c[1]), "+f"(c[2]), "+f"(c[3])
        : "r"(a[0]), "r"(a[1]), "r"(a[2]), "r"(a[3]), "r"(b0), "r"(b1));
}

__device__ __forceinline__ uint32_t sw128(uint32_t off) {
    return off ^ ((off >> 3) & 0x70);
}

// ---------------------------------------------------------------------------
// Kernel 1: LUT (matches XLA:GPU libdevice sinf/cosf of the f32 grid)
// ---------------------------------------------------------------------------
__global__ void rin_lut_kernel() {
    int i = blockIdx.x * blockDim.x + threadIdx.x;
    if (i < LUT_N) {
        float g = __fmul_rn((float)i, GRID_F);
        g_sin[i] = sinf(g);
        g_cos[i] = cosf(g);
    }
}

// ---------------------------------------------------------------------------
// Kernel 2: proj fp32 -> fp16
// ---------------------------------------------------------------------------
__global__ void rin_conv_kernel(const float* __restrict__ p) {
    size_t i = ((size_t)blockIdx.x * blockDim.x + threadIdx.x) * 4;
    if (i < (size_t)V_DIM * K_DIM) {
        float4 v = *(const float4*)(p + i);
        __half2 h0 = __floats2half2_rn(v.x, v.y);
        __half2 h1 = __floats2half2_rn(v.z, v.w);
        uint2 st;
        st.x = *(uint32_t*)&h0;
        st.y = *(uint32_t*)&h1;
        *(uint2*)(g_B + i) = st;
    }
}

// ---------------------------------------------------------------------------
// Kernel 3: sequential scan. 32 blocks x 32 threads: block = (b, d-chunk),
// 1024 independent chains spread over 32 SMs. Fused float2 LUT in smem:
// one LDS.64 on the critical dependency chain per theta.
// Bit-exact replication of the reference fp32 math; emb prefetched 8 deep.
// ---------------------------------------------------------------------------
#define PF 8
__global__ void __launch_bounds__(32) rin_scan_kernel(
        const int* __restrict__ ids, const float* __restrict__ emb) {
    __shared__ float2 s_sc[LUT_N];
    int b = blockIdx.x >> 3;
    int d = ((blockIdx.x & 7) << 5) + threadIdx.x;
    for (int i = threadIdx.x; i < LUT_N; i += 32)
        s_sc[i] = make_float2(g_sin[i], g_cos[i]);
    __syncthreads();

    const int* rid = ids + b * S_DIM;
    float hr = 0.0f, hi = 0.0f;

    float wp[PF], bp[PF];
#pragma unroll
    for (int j = 0; j < PF; j++) {
        int id = __ldg(rid + j);
        wp[j] = __ldg(emb + (size_t)id * K_DIM + d);
        bp[j] = __ldg(emb + (size_t)id * K_DIM + D_DIM + d);
    }

    __half* arow = g_A + (size_t)b * S_DIM * K_DIM + d;

    for (int s0 = 0; s0 < S_DIM; s0 += PF) {
#pragma unroll
        for (int j = 0; j < PF; j++) {
            int s = s0 + j;
            float w = wp[j];
            float bt = bp[j];
            if (s + PF < S_DIM) {
                int id = __ldg(rid + s + PF);
                wp[j] = __ldg(emb + (size_t)id * K_DIM + d);
                bp[j] = __ldg(emb + (size_t)id * K_DIM + D_DIM + d);
            }
            float lam = __fadd_rn(1.0f, fabsf(w));
            float tp  = __fmul_rn((float)s, PHI_F);
            float tr  = __fadd_rn(__fadd_rn(__fdiv_rn(hr, lam), bt), tp);
            float ti  = __fadd_rn(__fadd_rn(__fdiv_rn(hi, lam), bt), tp);
            int ir = __float2int_rd(__fmul_rn(tr, CINV_F)) & (LUT_N - 1);
            int ii = __float2int_rd(__fmul_rn(ti, CINV_F)) & (LUT_N - 1);
            float2 vr = s_sc[ir];     // (sin, cos)
            float2 vi = s_sc[ii];
            float nhr = __fsub_rn(__fmul_rn(vr.y, vi.y), __fmul_rn(vr.x, vi.x));
            float nhi = __fadd_rn(__fmul_rn(vr.y, vi.x), __fmul_rn(vr.x, vi.y));
            hr = nhr;
            hi = nhi;
            arow[(size_t)s * K_DIM]         = __float2half_rn(nhr);
            arow[(size_t)s * K_DIM + D_DIM] = __float2half_rn(nhi);
        }
    }
}

// ---------------------------------------------------------------------------
// Kernel 4: classic HMMA GEMM  C[8192,32000] = A[8192,512] * B[32000,512]^T
// CTA tile 128x256, K staged x64 (SW128 rows), cp.async double-buffered,
// 8 warps = 2(M) x 4(N), warp tile 64x64 (MMA:ldmatrix = 32:8).
// ---------------------------------------------------------------------------
#define A_TILE  16384                 // 128 rows * 128B
#define B_TILE  32768                 // 256 rows * 128B
#define STAGE_SZ (A_TILE + B_TILE)    // 49152
#define SM_TOTAL (2 * STAGE_SZ)       // 98304

__device__ __forceinline__ void gemm_load_stage(uint32_t sb, int stage, int kc,
                                                int m0, int n0, int tid) {
    const __half* Ag = g_A + (size_t)m0 * K_DIM + kc * KC;
    const __half* Bg = g_B + (size_t)n0 * K_DIM + kc * KC;
    uint32_t abase = sb + stage * STAGE_SZ;
    uint32_t bbase = abase + A_TILE;
#pragma unroll
    for (int it = 0; it < 4; it++) {                // A: 1024 16B units
        int u = tid + it * 256;
        int r = u >> 3, c = u & 7;
        uint32_t off = (uint32_t)(r * 128 + c * 16);
        cp_async16(abase + sw128(off), Ag + (size_t)r * K_DIM + c * 8);
    }
#pragma unroll
    for (int it = 0; it < 8; it++) {                // B: 2048 16B units
        int u = tid + it * 256;
        int r = u >> 3, c = u & 7;
        uint32_t off = (uint32_t)(r * 128 + c * 16);
        cp_async16(bbase + sw128(off), Bg + (size_t)r * K_DIM + c * 8);
    }
    CP_COMMIT();
}

__global__ void __launch_bounds__(256, 1) rin_gemm_kernel(
        float* __restrict__ out, const float* __restrict__ bias) {
    extern __shared__ char smem[];
    uint32_t sb = smem_u32(smem);
    const int tid = threadIdx.x;
    const int lane = tid & 31;
    const int wid = tid >> 5;
    const int wm = wid & 1;          // 0..1  -> 64-row slab
    const int wn = wid >> 1;         // 0..3  -> 64-col slab
    const int n0 = blockIdx.x * TN;
    const int m0 = blockIdx.y * TM;

    float acc[4][8][4];
#pragma unroll
    for (int i = 0; i < 4; i++)
#pragma unroll
        for (int j = 0; j < 8; j++)
#pragma unroll
            for (int k = 0; k < 4; k++) acc[i][j][k] = 0.0f;

    gemm_load_stage(sb, 0, 0, m0, n0, tid);

    // per-lane ldmatrix row/seg components (stage-invariant)
    const int a_row  = wm * 64 + (lane & 15);                     // + i*16
    const int a_sega = (lane >> 4) * 16;                          // + ks*32
    const int b_row  = wn * 64 + (lane & 7) + ((lane >> 4) << 3); // + j*16
    const int b_sega = ((lane >> 3) & 1) * 16;                    // + ks*32

    for (int kc = 0; kc < NKC; kc++) {
        const int buf = kc & 1;
        CP_WAIT0();
        __syncthreads();
        if (kc + 1 < NKC)
            gemm_load_stage(sb, buf ^ 1, kc + 1, m0, n0, tid);

        const uint32_t abase = sb + buf * STAGE_SZ;
        const uint32_t bbase = abase + A_TILE;
#pragma unroll
        for (int ks = 0; ks < 4; ks++) {
            uint32_t ar[4][4];
#pragma unroll
            for (int i = 0; i < 4; i++) {
                uint32_t off = (uint32_t)((a_row + i * 16) * 128 + ks * 32 + a_sega);
                ldmatrix_x4(ar[i], abase + sw128(off));
            }
            uint32_t br[4][4];
#pragma unroll
            for (int j = 0; j < 4; j++) {
                uint32_t off = (uint32_t)((b_row + j * 16) * 128 + ks * 32 + b_sega);
                ldmatrix_x4(br[j], bbase + sw128(off));
            }
#pragma unroll
            for (int i = 0; i < 4; i++)
#pragma unroll
                for (int jj = 0; jj < 8; jj++)
                    mma16816(acc[i][jj], ar[i],
                             br[jj >> 1][(jj & 1) * 2],
                             br[jj >> 1][(jj & 1) * 2 + 1]);
        }
        __syncthreads();
    }

    // epilogue: direct stores with bias
    const int ncol0 = n0 + wn * 64;
#pragma unroll
    for (int i = 0; i < 4; i++) {
        int row = m0 + wm * 64 + i * 16 + (lane >> 2);
        float* o0 = out + (size_t)row * V_DIM + ncol0;
        float* o1 = o0 + (size_t)8 * V_DIM;
#pragma unroll
        for (int jj = 0; jj < 8; jj++) {
            int col = jj * 8 + (lane & 3) * 2;
            float bx = __ldg(bias + ncol0 + col);
            float by = __ldg(bias + ncol0 + col + 1);
            float2 v0 = make_float2(acc[i][jj][0] + bx, acc[i][jj][1] + by);
            float2 v1 = make_float2(acc[i][jj][2] + bx, acc[i][jj][3] + by);
            *(float2*)(o0 + col) = v0;
            *(float2*)(o1 + col) = v1;
        }
    }
}

// ---------------------------------------------------------------------------
// launch
// ---------------------------------------------------------------------------
extern "C" void kernel_launch(void* const* d_in, const int* in_sizes, int n_in,
                              void* d_out, int out_size) {
    const int*   ids  = (const int*)d_in[0];
    const float* emb  = (const float*)d_in[1];
    const float* proj = (const float*)d_in[2];
    const float* bias = (const float*)d_in[3];
    float* out = (float*)d_out;

    cudaFuncSetAttribute(rin_gemm_kernel,
                         cudaFuncAttributeMaxDynamicSharedMemorySize, SM_TOTAL);

    rin_lut_kernel<<<16, 256>>>();
    rin_conv_kernel<<<(V_DIM * K_DIM / 4 + 255) / 256, 256>>>(proj);
    rin_scan_kernel<<<32, 32>>>(ids, emb);
    rin_gemm_kernel<<<dim3(V_DIM / TN, M_DIM / TM), 256, SM_TOTAL>>>(out, bias);
}

// round 5
// speedup vs baseline: 1.0126x; 1.0126x over previous
#include <cuda_runtime.h>
#include <cuda_fp16.h>
#include <cstdint>
#include <cstddef>

// ---------------------------------------------------------------------------
// Problem constants
// ---------------------------------------------------------------------------
#define B_DIM 4
#define S_DIM 2048
#define V_DIM 32000
#define K_DIM 512            // 2*D
#define D_DIM 256
#define M_DIM 8192           // B*S
#define LUT_N 4096

// exact-double constants rounded to f32
#define PHI_F   1.6180339887498949f          // (1+sqrt5)/2
#define CINV_F  651.8986469044033f           // 4096 / (2*pi)
#define GRID_F  0.0015339807878856412f       // (2*pi) / 4096

// GEMM tiling
#define TM 128
#define TN 256
#define KC 64                // k elements per stage = 128 bytes fp16
#define NKC 8                // 512 / 64
#define NSTAGE 4

// scratch (device globals allowed; runtime alloc is not)
static __device__ __align__(256) float  g_sin[LUT_N];
static __device__ __align__(256) float  g_cos[LUT_N];
static __device__ __align__(256) __half g_A[(size_t)M_DIM * K_DIM];
static __device__ __align__(256) __half g_B[(size_t)V_DIM * K_DIM];

// ---------------------------------------------------------------------------
// PTX helpers (base-arch only: cp.async, ldmatrix, mma.sync)
// ---------------------------------------------------------------------------
__device__ __forceinline__ uint32_t smem_u32(const void* p) {
    return (uint32_t)__cvta_generic_to_shared(p);
}
__device__ __forceinline__ void cp_async16(uint32_t dst, const void* src) {
    asm volatile("cp.async.cg.shared.global [%0], [%1], 16;"
                 :: "r"(dst), "l"(src) : "memory");
}
#define CP_COMMIT() asm volatile("cp.async.commit_group;" ::: "memory")
#define CP_WAIT2()  asm volatile("cp.async.wait_group 2;" ::: "memory")

__device__ __forceinline__ void ldmatrix_x4(uint32_t* r, uint32_t addr) {
    asm volatile("ldmatrix.sync.aligned.m8n8.x4.shared.b16 {%0,%1,%2,%3}, [%4];"
                 : "=r"(r[0]), "=r"(r[1]), "=r"(r[2]), "=r"(r[3]) : "r"(addr));
}

__device__ __forceinline__ void mma16816(float* c, const uint32_t* a,
                                         uint32_t b0, uint32_t b1) {
    asm volatile(
        "mma.sync.aligned.m16n8k16.row.col.f32.f16.f16.f32 "
        "{%0,%1,%2,%3}, {%4,%5,%6,%7}, {%8,%9}, {%0,%1,%2,%3};"
        : "+f"(c[0]), "+f"(c[1]), "+f"(c[2]), "+f"(c[3])
        : "r"(a[0]), "r"(a[1]), "r"(a[2]), "r"(a[3]), "r"(b0), "r"(b1));
}

__device__ __forceinline__ uint32_t sw128(uint32_t off) {
    return off ^ ((off >> 3) & 0x70);
}

// ---------------------------------------------------------------------------
// Kernel 1: LUT (matches XLA:GPU libdevice sinf/cosf of the f32 grid)
// ---------------------------------------------------------------------------
__global__ void rin_lut_kernel() {
    int i = blockIdx.x * blockDim.x + threadIdx.x;
    if (i < LUT_N) {
        float g = __fmul_rn((float)i, GRID_F);
        g_sin[i] = sinf(g);
        g_cos[i] = cosf(g);
    }
}

// ---------------------------------------------------------------------------
// Kernel 2: proj fp32 -> fp16
// ---------------------------------------------------------------------------
__global__ void rin_conv_kernel(const float* __restrict__ p) {
    size_t i = ((size_t)blockIdx.x * blockDim.x + threadIdx.x) * 4;
    if (i < (size_t)V_DIM * K_DIM) {
        float4 v = *(const float4*)(p + i);
        __half2 h0 = __floats2half2_rn(v.x, v.y);
        __half2 h1 = __floats2half2_rn(v.z, v.w);
        uint2 st;
        st.x = *(uint32_t*)&h0;
        st.y = *(uint32_t*)&h1;
        *(uint2*)(g_B + i) = st;
    }
}

// ---------------------------------------------------------------------------
// Kernel 3: sequential scan. 32 blocks x 32 threads (1024 independent chains).
// Separate 4B-bank sin/cos LUTs in smem (two independent LDS.32 per theta).
// Bit-exact replication of the reference fp32 math; emb prefetched 8 deep.
// ---------------------------------------------------------------------------
#define PF 8
__global__ void __launch_bounds__(32) rin_scan_kernel(
        const int* __restrict__ ids, const float* __restrict__ emb) {
    __shared__ float s_sin[LUT_N];
    __shared__ float s_cos[LUT_N];
    int b = blockIdx.x >> 3;
    int d = ((blockIdx.x & 7) << 5) + threadIdx.x;
    for (int i = threadIdx.x; i < LUT_N; i += 32) {
        s_sin[i] = g_sin[i];
        s_cos[i] = g_cos[i];
    }
    __syncthreads();

    const int* rid = ids + b * S_DIM;
    float hr = 0.0f, hi = 0.0f;

    float wp[PF], bp[PF];
#pragma unroll
    for (int j = 0; j < PF; j++) {
        int id = __ldg(rid + j);
        wp[j] = __ldg(emb + (size_t)id * K_DIM + d);
        bp[j] = __ldg(emb + (size_t)id * K_DIM + D_DIM + d);
    }

    __half* arow = g_A + (size_t)b * S_DIM * K_DIM + d;

    for (int s0 = 0; s0 < S_DIM; s0 += PF) {
#pragma unroll
        for (int j = 0; j < PF; j++) {
            int s = s0 + j;
            float w = wp[j];
            float bt = bp[j];
            if (s + PF < S_DIM) {
                int id = __ldg(rid + s + PF);
                wp[j] = __ldg(emb + (size_t)id * K_DIM + d);
                bp[j] = __ldg(emb + (size_t)id * K_DIM + D_DIM + d);
            }
            float lam = __fadd_rn(1.0f, fabsf(w));
            float tp  = __fmul_rn((float)s, PHI_F);
            float tr  = __fadd_rn(__fadd_rn(__fdiv_rn(hr, lam), bt), tp);
            float ti  = __fadd_rn(__fadd_rn(__fdiv_rn(hi, lam), bt), tp);
            int ir = __float2int_rd(__fmul_rn(tr, CINV_F)) & (LUT_N - 1);
            int ii = __float2int_rd(__fmul_rn(ti, CINV_F)) & (LUT_N - 1);
            float sr = s_sin[ir], cr = s_cos[ir];
            float si = s_sin[ii], ci = s_cos[ii];
            float nhr = __fsub_rn(__fmul_rn(cr, ci), __fmul_rn(sr, si));
            float nhi = __fadd_rn(__fmul_rn(cr, si), __fmul_rn(sr, ci));
            hr = nhr;
            hi = nhi;
            arow[(size_t)s * K_DIM]         = __float2half_rn(nhr);
            arow[(size_t)s * K_DIM + D_DIM] = __float2half_rn(nhi);
        }
    }
}

// ---------------------------------------------------------------------------
// Kernel 4: classic HMMA GEMM  C[8192,32000] = A[8192,512] * B[32000,512]^T
// CTA tile 128x256, warp tile 64x64, 4-stage cp.async pipeline (wait_group 2),
// SW128-swizzled 128B rows, 8 warps = 2(M) x 4(N).
// ---------------------------------------------------------------------------
#define A_TILE  16384                 // 128 rows * 128B
#define B_TILE  32768                 // 256 rows * 128B
#define STAGE_SZ (A_TILE + B_TILE)    // 49152
#define SM_TOTAL (NSTAGE * STAGE_SZ)  // 196608

__device__ __forceinline__ void gemm_load_stage(uint32_t sb, int stage, int kc,
                                                int m0, int n0, int tid) {
    const __half* Ag = g_A + (size_t)m0 * K_DIM + kc * KC;
    const __half* Bg = g_B + (size_t)n0 * K_DIM + kc * KC;
    uint32_t abase = sb + stage * STAGE_SZ;
    uint32_t bbase = abase + A_TILE;
#pragma unroll
    for (int it = 0; it < 4; it++) {                // A: 1024 16B units
        int u = tid + it * 256;
        int r = u >> 3, c = u & 7;
        uint32_t off = (uint32_t)(r * 128 + c * 16);
        cp_async16(abase + sw128(off), Ag + (size_t)r * K_DIM + c * 8);
    }
#pragma unroll
    for (int it = 0; it < 8; it++) {                // B: 2048 16B units
        int u = tid + it * 256;
        int r = u >> 3, c = u & 7;
        uint32_t off = (uint32_t)(r * 128 + c * 16);
        cp_async16(bbase + sw128(off), Bg + (size_t)r * K_DIM + c * 8);
    }
    CP_COMMIT();
}

__global__ void __launch_bounds__(256, 1) rin_gemm_kernel(
        float* __restrict__ out, const float* __restrict__ bias) {
    extern __shared__ char smem[];
    uint32_t sb = smem_u32(smem);
    const int tid = threadIdx.x;
    const int lane = tid & 31;
    const int wid = tid >> 5;
    const int wm = wid & 1;          // 0..1  -> 64-row slab
    const int wn = wid >> 1;         // 0..3  -> 64-col slab
    const int n0 = blockIdx.x * TN;
    const int m0 = blockIdx.y * TM;

    float acc[4][8][4];
#pragma unroll
    for (int i = 0; i < 4; i++)
#pragma unroll
        for (int j = 0; j < 8; j++)
#pragma unroll
            for (int k = 0; k < 4; k++) acc[i][j][k] = 0.0f;

    // prefetch 3 stages
    gemm_load_stage(sb, 0, 0, m0, n0, tid);
    gemm_load_stage(sb, 1, 1, m0, n0, tid);
    gemm_load_stage(sb, 2, 2, m0, n0, tid);

    // per-lane ldmatrix row/seg components (stage-invariant)
    const int a_row  = wm * 64 + (lane & 15);                     // + i*16
    const int a_sega = (lane >> 4) * 16;                          // + ks*32
    const int b_row  = wn * 64 + (lane & 7) + ((lane >> 4) << 3); // + j*16
    const int b_sega = ((lane >> 3) & 1) * 16;                    // + ks*32

    for (int kc = 0; kc < NKC; kc++) {
        const int buf = kc & (NSTAGE - 1);
        CP_WAIT2();                    // stage kc complete (issued 3 phases ago)
        __syncthreads();               // visibility + buffer-reuse guard
        if (kc + 3 < NKC)
            gemm_load_stage(sb, (kc + 3) & (NSTAGE - 1), kc + 3, m0, n0, tid);

        const uint32_t abase = sb + buf * STAGE_SZ;
        const uint32_t bbase = abase + A_TILE;
#pragma unroll
        for (int ks = 0; ks < 4; ks++) {
            uint32_t ar[4][4];
#pragma unroll
            for (int i = 0; i < 4; i++) {
                uint32_t off = (uint32_t)((a_row + i * 16) * 128 + ks * 32 + a_sega);
                ldmatrix_x4(ar[i], abase + sw128(off));
            }
            uint32_t br[4][4];
#pragma unroll
            for (int j = 0; j < 4; j++) {
                uint32_t off = (uint32_t)((b_row + j * 16) * 128 + ks * 32 + b_sega);
                ldmatrix_x4(br[j], bbase + sw128(off));
            }
#pragma unroll
            for (int i = 0; i < 4; i++)
#pragma unroll
                for (int jj = 0; jj < 8; jj++)
                    mma16816(acc[i][jj], ar[i],
                             br[jj >> 1][(jj & 1) * 2],
                             br[jj >> 1][(jj & 1) * 2 + 1]);
        }
    }

    // epilogue: direct stores with bias
    const int ncol0 = n0 + wn * 64;
#pragma unroll
    for (int i = 0; i < 4; i++) {
        int row = m0 + wm * 64 + i * 16 + (lane >> 2);
        float* o0 = out + (size_t)row * V_DIM + ncol0;
        float* o1 = o0 + (size_t)8 * V_DIM;
#pragma unroll
        for (int jj = 0; jj < 8; jj++) {
            int col = jj * 8 + (lane & 3) * 2;
            float bx = __ldg(bias + ncol0 + col);
            float by = __ldg(bias + ncol0 + col + 1);
            float2 v0 = make_float2(acc[i][jj][0] + bx, acc[i][jj][1] + by);
            float2 v1 = make_float2(acc[i][jj][2] + bx, acc[i][jj][3] + by);
            *(float2*)(o0 + col) = v0;
            *(float2*)(o1 + col) = v1;
        }
    }
}

// ---------------------------------------------------------------------------
// launch
// ---------------------------------------------------------------------------
extern "C" void kernel_launch(void* const* d_in, const int* in_sizes, int n_in,
                              void* d_out, int out_size) {
    const int*   ids  = (const int*)d_in[0];
    const float* emb  = (const float*)d_in[1];
    const float* proj = (const float*)d_in[2];
    const float* bias = (const float*)d_in[3];
    float* out = (float*)d_out;

    cudaFuncSetAttribute(rin_gemm_kernel,
                         cudaFuncAttributeMaxDynamicSharedMemorySize, SM_TOTAL);

    rin_lut_kernel<<<16, 256>>>();
    rin_conv_kernel<<<(V_DIM * K_DIM / 4 + 255) / 256, 256>>>(proj);
    rin_scan_kernel<<<32, 32>>>(ids, emb);
    rin_gemm_kernel<<<dim3(V_DIM / TN, M_DIM / TM), 256, SM_TOTAL>>>(out, bias);
}

// round 6
// speedup vs baseline: 1.1747x; 1.1601x over previous
#include <cuda_runtime.h>
#include <cuda_fp16.h>
#include <cstdint>
#include <cstddef>

// ---------------------------------------------------------------------------
// Problem constants
// ---------------------------------------------------------------------------
#define B_DIM 4
#define S_DIM 2048
#define V_DIM 32000
#define K_DIM 512            // 2*D
#define D_DIM 256
#define M_DIM 8192           // B*S
#define LUT_N 4096

// exact-double constants rounded to f32
#define PHI_F   1.6180339887498949f          // (1+sqrt5)/2
#define CINV_F  651.8986469044033f           // 4096 / (2*pi)
#define GRID_F  0.0015339807878856412f       // (2*pi) / 4096

// GEMM tiling
#define TM 128
#define TN 128
#define KC 64                // k elements per stage = 128 bytes fp16
#define NKC 8                // 512 / 64
#define NSTAGE 3

// scratch (device globals allowed; runtime alloc is not)
static __device__ __align__(256) float  g_sin[LUT_N];
static __device__ __align__(256) float  g_cos[LUT_N];
static __device__ __align__(256) __half g_A[(size_t)M_DIM * K_DIM];
static __device__ __align__(256) __half g_B[(size_t)V_DIM * K_DIM];

// ---------------------------------------------------------------------------
// PTX helpers (base-arch only: cp.async, ldmatrix, mma.sync)
// ---------------------------------------------------------------------------
__device__ __forceinline__ uint32_t smem_u32(const void* p) {
    return (uint32_t)__cvta_generic_to_shared(p);
}
__device__ __forceinline__ void cp_async16(uint32_t dst, const void* src) {
    asm volatile("cp.async.cg.shared.global [%0], [%1], 16;"
                 :: "r"(dst), "l"(src) : "memory");
}
#define CP_COMMIT() asm volatile("cp.async.commit_group;" ::: "memory")
#define CP_WAIT1()  asm volatile("cp.async.wait_group 1;" ::: "memory")

__device__ __forceinline__ void ldmatrix_x4(uint32_t* r, uint32_t addr) {
    asm volatile("ldmatrix.sync.aligned.m8n8.x4.shared.b16 {%0,%1,%2,%3}, [%4];"
                 : "=r"(r[0]), "=r"(r[1]), "=r"(r[2]), "=r"(r[3]) : "r"(addr));
}

__device__ __forceinline__ void mma16816(float* c, const uint32_t* a,
                                         uint32_t b0, uint32_t b1) {
    asm volatile(
        "mma.sync.aligned.m16n8k16.row.col.f32.f16.f16.f32 "
        "{%0,%1,%2,%3}, {%4,%5,%6,%7}, {%8,%9}, {%0,%1,%2,%3};"
        : "+f"(c[0]), "+f"(c[1]), "+f"(c[2]), "+f"(c[3])
        : "r"(a[0]), "r"(a[1]), "r"(a[2]), "r"(a[3]), "r"(b0), "r"(b1));
}

__device__ __forceinline__ uint32_t sw128(uint32_t off) {
    return off ^ ((off >> 3) & 0x70);
}

// Guard-free correctly-rounded fp32 division (Markstein). Valid for normal
// a, b with no overflow in intermediates — here |a|<=1, b in [1, ~3].
// rcp.approx + 2x Newton gives r within 0.5ulp of 1/b; the fma-based
// remainder correction then yields the round-to-nearest quotient exactly.
__device__ __forceinline__ float div_rn_fast(float a, float b) {
    float r;
    asm("rcp.approx.f32 %0, %1;" : "=f"(r) : "f"(b));
    float e = __fmaf_rn(-b, r, 1.0f);
    r = __fmaf_rn(r, e, r);
    e = __fmaf_rn(-b, r, 1.0f);
    r = __fmaf_rn(r, e, r);
    float q = __fmul_rn(a, r);
    float rem = __fmaf_rn(-b, q, a);
    return __fmaf_rn(rem, r, q);
}

// ---------------------------------------------------------------------------
// Kernel 1: LUT (matches XLA:GPU libdevice sinf/cosf of the f32 grid)
// ---------------------------------------------------------------------------
__global__ void rin_lut_kernel() {
    int i = blockIdx.x * blockDim.x + threadIdx.x;
    if (i < LUT_N) {
        float g = __fmul_rn((float)i, GRID_F);
        g_sin[i] = sinf(g);
        g_cos[i] = cosf(g);
    }
}

// ---------------------------------------------------------------------------
// Kernel 2: proj fp32 -> fp16
// ---------------------------------------------------------------------------
__global__ void rin_conv_kernel(const float* __restrict__ p) {
    size_t i = ((size_t)blockIdx.x * blockDim.x + threadIdx.x) * 4;
    if (i < (size_t)V_DIM * K_DIM) {
        float4 v = *(const float4*)(p + i);
        __half2 h0 = __floats2half2_rn(v.x, v.y);
        __half2 h1 = __floats2half2_rn(v.z, v.w);
        uint2 st;
        st.x = *(uint32_t*)&h0;
        st.y = *(uint32_t*)&h1;
        *(uint2*)(g_B + i) = st;
    }
}

// ---------------------------------------------------------------------------
// Kernel 3: sequential scan. 32 blocks x 32 threads (1024 independent chains).
// Guard-free correctly-rounded division shortens the per-step dependency
// chain from ~390 to ~120 cycles. All other ops bit-exact vs reference.
// ---------------------------------------------------------------------------
#define PF 8
__global__ void __launch_bounds__(32) rin_scan_kernel(
        const int* __restrict__ ids, const float* __restrict__ emb) {
    __shared__ float s_sin[LUT_N];
    __shared__ float s_cos[LUT_N];
    int b = blockIdx.x >> 3;
    int d = ((blockIdx.x & 7) << 5) + threadIdx.x;
    for (int i = threadIdx.x; i < LUT_N; i += 32) {
        s_sin[i] = g_sin[i];
        s_cos[i] = g_cos[i];
    }
    __syncthreads();

    const int* rid = ids + b * S_DIM;
    float hr = 0.0f, hi = 0.0f;

    float wp[PF], bp[PF];
#pragma unroll
    for (int j = 0; j < PF; j++) {
        int id = __ldg(rid + j);
        wp[j] = __ldg(emb + (size_t)id * K_DIM + d);
        bp[j] = __ldg(emb + (size_t)id * K_DIM + D_DIM + d);
    }

    __half* arow = g_A + (size_t)b * S_DIM * K_DIM + d;

    for (int s0 = 0; s0 < S_DIM; s0 += PF) {
#pragma unroll
        for (int j = 0; j < PF; j++) {
            int s = s0 + j;
            float w = wp[j];
            float bt = bp[j];
            if (s + PF < S_DIM) {
                int id = __ldg(rid + s + PF);
                wp[j] = __ldg(emb + (size_t)id * K_DIM + d);
                bp[j] = __ldg(emb + (size_t)id * K_DIM + D_DIM + d);
            }
            float lam = __fadd_rn(1.0f, fabsf(w));
            float tp  = __fmul_rn((float)s, PHI_F);
            float tr  = __fadd_rn(__fadd_rn(div_rn_fast(hr, lam), bt), tp);
            float ti  = __fadd_rn(__fadd_rn(div_rn_fast(hi, lam), bt), tp);
            int ir = __float2int_rd(__fmul_rn(tr, CINV_F)) & (LUT_N - 1);
            int ii = __float2int_rd(__fmul_rn(ti, CINV_F)) & (LUT_N - 1);
            float sr = s_sin[ir], cr = s_cos[ir];
            float si = s_sin[ii], ci = s_cos[ii];
            float nhr = __fsub_rn(__fmul_rn(cr, ci), __fmul_rn(sr, si));
            float nhi = __fadd_rn(__fmul_rn(cr, si), __fmul_rn(sr, ci));
            hr = nhr;
            hi = nhi;
            arow[(size_t)s * K_DIM]         = __float2half_rn(nhr);
            arow[(size_t)s * K_DIM + D_DIM] = __float2half_rn(nhi);
        }
    }
}

// ---------------------------------------------------------------------------
// Kernel 4: classic HMMA GEMM  C[8192,32000] = A[8192,512] * B[32000,512]^T
// CTA tile 128x128 (2 CTAs/SM, 16 warps/SM), warp tile 64x32, 3-stage
// cp.async pipeline with wait_group 1, SW128-swizzled 128B rows.
// ---------------------------------------------------------------------------
#define A_TILE  16384                 // 128 rows * 128B
#define B_TILE  16384
#define STAGE_SZ (A_TILE + B_TILE)    // 32768
#define SM_TOTAL (NSTAGE * STAGE_SZ)  // 98304 per CTA

__device__ __forceinline__ void gemm_load_stage(uint32_t sb, int stage, int kc,
                                                int m0, int n0, int tid) {
    const __half* Ag = g_A + (size_t)m0 * K_DIM + kc * KC;
    const __half* Bg = g_B + (size_t)n0 * K_DIM + kc * KC;
    uint32_t abase = sb + stage * STAGE_SZ;
    uint32_t bbase = abase + A_TILE;
#pragma unroll
    for (int it = 0; it < 4; it++) {                // A: 1024 16B units
        int u = tid + it * 256;
        int r = u >> 3, c = u & 7;
        uint32_t off = (uint32_t)(r * 128 + c * 16);
        cp_async16(abase + sw128(off), Ag + (size_t)r * K_DIM + c * 8);
    }
#pragma unroll
    for (int it = 0; it < 4; it++) {                // B: 1024 16B units
        int u = tid + it * 256;
        int r = u >> 3, c = u & 7;
        uint32_t off = (uint32_t)(r * 128 + c * 16);
        cp_async16(bbase + sw128(off), Bg + (size_t)r * K_DIM + c * 8);
    }
    CP_COMMIT();
}

__global__ void __launch_bounds__(256, 2) rin_gemm_kernel(
        float* __restrict__ out, const float* __restrict__ bias) {
    extern __shared__ char smem[];
    uint32_t sb = smem_u32(smem);
    const int tid = threadIdx.x;
    const int lane = tid & 31;
    const int wid = tid >> 5;
    const int wm = wid & 1;          // 0..1  -> 64-row slab
    const int wn = wid >> 1;         // 0..3  -> 32-col slab
    const int n0 = blockIdx.x * TN;
    const int m0 = blockIdx.y * TM;

    float acc[4][4][4];
#pragma unroll
    for (int i = 0; i < 4; i++)
#pragma unroll
        for (int j = 0; j < 4; j++)
#pragma unroll
            for (int k = 0; k < 4; k++) acc[i][j][k] = 0.0f;

    // prefetch 2 stages
    gemm_load_stage(sb, 0, 0, m0, n0, tid);
    gemm_load_stage(sb, 1, 1, m0, n0, tid);

    // per-lane ldmatrix row/seg components (stage-invariant)
    const int a_row  = wm * 64 + (lane & 15);                     // + i*16
    const int a_sega = (lane >> 4) * 16;                          // + ks*32
    const int b_row  = wn * 32 + (lane & 7) + ((lane >> 4) << 3); // + j*16
    const int b_sega = ((lane >> 3) & 1) * 16;                    // + ks*32

    int buf = 0;
    for (int kc = 0; kc < NKC; kc++) {
        CP_WAIT1();                    // stage kc complete; kc+1 may still fly
        __syncthreads();               // visibility + buffer-reuse guard
        if (kc + 2 < NKC)
            gemm_load_stage(sb, (buf + 2 >= NSTAGE) ? buf + 2 - NSTAGE : buf + 2,
                            kc + 2, m0, n0, tid);

        const uint32_t abase = sb + buf * STAGE_SZ;
        const uint32_t bbase = abase + A_TILE;
#pragma unroll
        for (int ks = 0; ks < 4; ks++) {
            uint32_t ar[4][4];
#pragma unroll
            for (int i = 0; i < 4; i++) {
                uint32_t off = (uint32_t)((a_row + i * 16) * 128 + ks * 32 + a_sega);
                ldmatrix_x4(ar[i], abase + sw128(off));
            }
            uint32_t br[2][4];
#pragma unroll
            for (int j = 0; j < 2; j++) {
                uint32_t off = (uint32_t)((b_row + j * 16) * 128 + ks * 32 + b_sega);
                ldmatrix_x4(br[j], bbase + sw128(off));
            }
#pragma unroll
            for (int i = 0; i < 4; i++)
#pragma unroll
                for (int jj = 0; jj < 4; jj++)
                    mma16816(acc[i][jj], ar[i],
                             br[jj >> 1][(jj & 1) * 2],
                             br[jj >> 1][(jj & 1) * 2 + 1]);
        }
        buf = (buf + 1 == NSTAGE) ? 0 : buf + 1;
    }

    // epilogue: direct stores with bias
    const int ncol0 = n0 + wn * 32;
#pragma unroll
    for (int i = 0; i < 4; i++) {
        int row = m0 + wm * 64 + i * 16 + (lane >> 2);
        float* o0 = out + (size_t)row * V_DIM + ncol0;
        float* o1 = o0 + (size_t)8 * V_DIM;
#pragma unroll
        for (int jj = 0; jj < 4; jj++) {
            int col = jj * 8 + (lane & 3) * 2;
            float bx = __ldg(bias + ncol0 + col);
            float by = __ldg(bias + ncol0 + col + 1);
            float2 v0 = make_float2(acc[i][jj][0] + bx, acc[i][jj][1] + by);
            float2 v1 = make_float2(acc[i][jj][2] + bx, acc[i][jj][3] + by);
            *(float2*)(o0 + col) = v0;
            *(float2*)(o1 + col) = v1;
        }
    }
}

// ---------------------------------------------------------------------------
// launch
// ---------------------------------------------------------------------------
extern "C" void kernel_launch(void* const* d_in, const int* in_sizes, int n_in,
                              void* d_out, int out_size) {
    const int*   ids  = (const int*)d_in[0];
    const float* emb  = (const float*)d_in[1];
    const float* proj = (const float*)d_in[2];
    const float* bias = (const float*)d_in[3];
    float* out = (float*)d_out;

    cudaFuncSetAttribute(rin_gemm_kernel,
                         cudaFuncAttributeMaxDynamicSharedMemorySize, SM_TOTAL);

    rin_lut_kernel<<<16, 256>>>();
    rin_conv_kernel<<<(V_DIM * K_DIM / 4 + 255) / 256, 256>>>(proj);
    rin_scan_kernel<<<32, 32>>>(ids, emb);
    rin_gemm_kernel<<<dim3(V_DIM / TN, M_DIM / TM), 256, SM_TOTAL>>>(out, bias);
}

// round 7
// speedup vs baseline: 1.3451x; 1.1450x over previous
#include <cuda_runtime.h>
#include <cuda_fp16.h>
#include <cstdint>
#include <cstddef>

// ---------------------------------------------------------------------------
// Problem constants
// ---------------------------------------------------------------------------
#define B_DIM 4
#define S_DIM 2048
#define V_DIM 32000
#define K_DIM 512            // 2*D
#define D_DIM 256
#define M_DIM 8192           // B*S
#define LUT_N 4096

// exact-double constants rounded to f32
#define PHI_F   1.6180339887498949f          // (1+sqrt5)/2
#define CINV_F  651.8986469044033f           // 4096 / (2*pi)
#define GRID_F  0.0015339807878856412f       // (2*pi) / 4096

// GEMM tiling
#define TM 128
#define TN 128
#define KC 64                // k elements per stage = 128 bytes fp16
#define NKC 8                // 512 / 64
#define NSTAGE 3

#define NSCAN 32             // scan blocks (8 per batch)
#define NTILE_N (V_DIM / TN) // 250
#define NTILE_M (M_DIM / TM) // 64

// scratch (device globals allowed; runtime alloc is not)
static __device__ __align__(256) __half g_A[(size_t)M_DIM * K_DIM];
static __device__ __align__(256) __half g_B[(size_t)V_DIM * K_DIM];
static __device__ int g_prog[NSCAN];   // per-scan-block step progress

// ---------------------------------------------------------------------------
// PTX helpers (base-arch only: cp.async, ldmatrix, mma.sync)
// ---------------------------------------------------------------------------
__device__ __forceinline__ uint32_t smem_u32(const void* p) {
    return (uint32_t)__cvta_generic_to_shared(p);
}
__device__ __forceinline__ void cp_async16(uint32_t dst, const void* src) {
    asm volatile("cp.async.cg.shared.global [%0], [%1], 16;"
                 :: "r"(dst), "l"(src) : "memory");
}
#define CP_COMMIT() asm volatile("cp.async.commit_group;" ::: "memory")
#define CP_WAIT1()  asm volatile("cp.async.wait_group 1;" ::: "memory")

__device__ __forceinline__ void ldmatrix_x4(uint32_t* r, uint32_t addr) {
    asm volatile("ldmatrix.sync.aligned.m8n8.x4.shared.b16 {%0,%1,%2,%3}, [%4];"
                 : "=r"(r[0]), "=r"(r[1]), "=r"(r[2]), "=r"(r[3]) : "r"(addr));
}

__device__ __forceinline__ void mma16816(float* c, const uint32_t* a,
                                         uint32_t b0, uint32_t b1) {
    asm volatile(
        "mma.sync.aligned.m16n8k16.row.col.f32.f16.f16.f32 "
        "{%0,%1,%2,%3}, {%4,%5,%6,%7}, {%8,%9}, {%0,%1,%2,%3};"
        : "+f"(c[0]), "+f"(c[1]), "+f"(c[2]), "+f"(c[3])
        : "r"(a[0]), "r"(a[1]), "r"(a[2]), "r"(a[3]), "r"(b0), "r"(b1));
}

__device__ __forceinline__ uint32_t sw128(uint32_t off) {
    return off ^ ((off >> 3) & 0x70);
}

__device__ __forceinline__ int ld_acq(const int* p) {
    int v;
    asm volatile("ld.acquire.gpu.global.b32 %0, [%1];" : "=r"(v) : "l"(p));
    return v;
}
__device__ __forceinline__ void st_rel(int* p, int v) {
    asm volatile("st.release.gpu.global.b32 [%0], %1;" :: "l"(p), "r"(v) : "memory");
}

// Guard-free correctly-rounded fp32 division (Markstein). Valid for normal
// a, b with no overflow in intermediates — here |a|<=1, b in [1, ~3].
__device__ __forceinline__ float div_rn_fast(float a, float b) {
    float r;
    asm("rcp.approx.f32 %0, %1;" : "=f"(r) : "f"(b));
    float e = __fmaf_rn(-b, r, 1.0f);
    r = __fmaf_rn(r, e, r);
    e = __fmaf_rn(-b, r, 1.0f);
    r = __fmaf_rn(r, e, r);
    float q = __fmul_rn(a, r);
    float rem = __fmaf_rn(-b, q, a);
    return __fmaf_rn(rem, r, q);
}

// ---------------------------------------------------------------------------
// Kernel A: proj fp32 -> fp16, plus progress-flag reset (runs before fused)
// ---------------------------------------------------------------------------
__global__ void rin_conv_kernel(const float* __restrict__ p) {
    if (blockIdx.x == 0 && threadIdx.x < NSCAN) g_prog[threadIdx.x] = 0;
    size_t i = ((size_t)blockIdx.x * blockDim.x + threadIdx.x) * 4;
    if (i < (size_t)V_DIM * K_DIM) {
        float4 v = *(const float4*)(p + i);
        __half2 h0 = __floats2half2_rn(v.x, v.y);
        __half2 h1 = __floats2half2_rn(v.z, v.w);
        uint2 st;
        st.x = *(uint32_t*)&h0;
        st.y = *(uint32_t*)&h1;
        *(uint2*)(g_B + i) = st;
    }
}

// ---------------------------------------------------------------------------
// Fused kernel: bids 0..31 = scan producers, bids 32.. = GEMM consumers.
// Scan publishes progress every 128 steps; GEMM m-tiles spin (acquire) until
// their 128 A-rows are complete, then run the R6-proven HMMA mainloop.
// ---------------------------------------------------------------------------
#define A_TILE  16384                 // 128 rows * 128B
#define B_TILE  16384
#define STAGE_SZ (A_TILE + B_TILE)    // 32768
#define SM_TOTAL (NSTAGE * STAGE_SZ)  // 98304 per CTA

#define PF 8

__device__ __forceinline__ void gemm_load_stage(uint32_t sb, int stage, int kc,
                                                int m0, int n0, int tid) {
    const __half* Ag = g_A + (size_t)m0 * K_DIM + kc * KC;
    const __half* Bg = g_B + (size_t)n0 * K_DIM + kc * KC;
    uint32_t abase = sb + stage * STAGE_SZ;
    uint32_t bbase = abase + A_TILE;
#pragma unroll
    for (int it = 0; it < 4; it++) {                // A: 1024 16B units
        int u = tid + it * 256;
        int r = u >> 3, c = u & 7;
        uint32_t off = (uint32_t)(r * 128 + c * 16);
        cp_async16(abase + sw128(off), Ag + (size_t)r * K_DIM + c * 8);
    }
#pragma unroll
    for (int it = 0; it < 4; it++) {                // B: 1024 16B units
        int u = tid + it * 256;
        int r = u >> 3, c = u & 7;
        uint32_t off = (uint32_t)(r * 128 + c * 16);
        cp_async16(bbase + sw128(off), Bg + (size_t)r * K_DIM + c * 8);
    }
    CP_COMMIT();
}

__global__ void __launch_bounds__(256, 2) rin_fused_kernel(
        const int* __restrict__ ids, const float* __restrict__ emb,
        float* __restrict__ out, const float* __restrict__ bias) {
    extern __shared__ char smem[];
    const int tid = threadIdx.x;

    if (blockIdx.x < NSCAN) {
        // ------------------------- scan producer -------------------------
        float* s_sin = (float*)smem;
        float* s_cos = s_sin + LUT_N;
        for (int i = tid; i < LUT_N; i += 256) {
            float g = __fmul_rn((float)i, GRID_F);
            s_sin[i] = sinf(g);
            s_cos[i] = cosf(g);
        }
        __syncthreads();
        if (tid >= 32) return;                 // only warp 0 runs chains

        const int bid = blockIdx.x;
        const int b = bid >> 3;
        const int d = ((bid & 7) << 5) + tid;

        const int* rid = ids + b * S_DIM;
        float hr = 0.0f, hi = 0.0f;

        float wp[PF], bp[PF];
#pragma unroll
        for (int j = 0; j < PF; j++) {
            int id = __ldg(rid + j);
            wp[j] = __ldg(emb + (size_t)id * K_DIM + d);
            bp[j] = __ldg(emb + (size_t)id * K_DIM + D_DIM + d);
        }

        __half* arow = g_A + (size_t)b * S_DIM * K_DIM + d;

        for (int s0 = 0; s0 < S_DIM; s0 += PF) {
#pragma unroll
            for (int j = 0; j < PF; j++) {
                int s = s0 + j;
                float w = wp[j];
                float bt = bp[j];
                if (s + PF < S_DIM) {
                    int id = __ldg(rid + s + PF);
                    wp[j] = __ldg(emb + (size_t)id * K_DIM + d);
                    bp[j] = __ldg(emb + (size_t)id * K_DIM + D_DIM + d);
                }
                float lam = __fadd_rn(1.0f, fabsf(w));
                float tp  = __fmul_rn((float)s, PHI_F);
                float tr  = __fadd_rn(__fadd_rn(div_rn_fast(hr, lam), bt), tp);
                float ti  = __fadd_rn(__fadd_rn(div_rn_fast(hi, lam), bt), tp);
                int ir = __float2int_rd(__fmul_rn(tr, CINV_F)) & (LUT_N - 1);
                int ii = __float2int_rd(__fmul_rn(ti, CINV_F)) & (LUT_N - 1);
                float sr = s_sin[ir], cr = s_cos[ir];
                float si = s_sin[ii], ci = s_cos[ii];
                float nhr = __fsub_rn(__fmul_rn(cr, ci), __fmul_rn(sr, si));
                float nhi = __fadd_rn(__fmul_rn(cr, si), __fmul_rn(sr, ci));
                hr = nhr;
                hi = nhi;
                arow[(size_t)s * K_DIM]         = __float2half_rn(nhr);
                arow[(size_t)s * K_DIM + D_DIM] = __float2half_rn(nhi);
            }
            if (((s0 + PF) & 127) == 0) {       // publish every 128 steps
                __threadfence();
                __syncwarp();
                if (tid == 0) st_rel(&g_prog[bid], s0 + PF);
            }
        }
        return;
    }

    // --------------------------- GEMM consumer ---------------------------
    uint32_t sb = smem_u32(smem);
    const int g = blockIdx.x - NSCAN;
    const int m0 = (g / NTILE_N) * TM;       // m-major: early bids ready first
    const int n0 = (g % NTILE_N) * TN;
    const int lane = tid & 31;
    const int wid = tid >> 5;
    const int wm = wid & 1;
    const int wn = wid >> 1;

    // wait until this tile's 128 A-rows are produced by all 8 scan blocks of b
    {
        const int b = m0 >> 11;
        const int s_end = (m0 & 2047) + TM;
        if (tid < 8) {
            const int* fp = &g_prog[b * 8 + tid];
            while (ld_acq(fp) < s_end) __nanosleep(128);
        }
        __syncthreads();
    }

    float acc[4][4][4];
#pragma unroll
    for (int i = 0; i < 4; i++)
#pragma unroll
        for (int j = 0; j < 4; j++)
#pragma unroll
            for (int k = 0; k < 4; k++) acc[i][j][k] = 0.0f;

    gemm_load_stage(sb, 0, 0, m0, n0, tid);
    gemm_load_stage(sb, 1, 1, m0, n0, tid);

    const int a_row  = wm * 64 + (lane & 15);
    const int a_sega = (lane >> 4) * 16;
    const int b_row  = wn * 32 + (lane & 7) + ((lane >> 4) << 3);
    const int b_sega = ((lane >> 3) & 1) * 16;

    int buf = 0;
    for (int kc = 0; kc < NKC; kc++) {
        CP_WAIT1();
        __syncthreads();
        if (kc + 2 < NKC)
            gemm_load_stage(sb, (buf + 2 >= NSTAGE) ? buf + 2 - NSTAGE : buf + 2,
                            kc + 2, m0, n0, tid);

        const uint32_t abase = sb + buf * STAGE_SZ;
        const uint32_t bbase = abase + A_TILE;
#pragma unroll
        for (int ks = 0; ks < 4; ks++) {
            uint32_t ar[4][4];
#pragma unroll
            for (int i = 0; i < 4; i++) {
                uint32_t off = (uint32_t)((a_row + i * 16) * 128 + ks * 32 + a_sega);
                ldmatrix_x4(ar[i], abase + sw128(off));
            }
            uint32_t br[2][4];
#pragma unroll
            for (int j = 0; j < 2; j++) {
                uint32_t off = (uint32_t)((b_row + j * 16) * 128 + ks * 32 + b_sega);
                ldmatrix_x4(br[j], bbase + sw128(off));
            }
#pragma unroll
            for (int i = 0; i < 4; i++)
#pragma unroll
                for (int jj = 0; jj < 4; jj++)
                    mma16816(acc[i][jj], ar[i],
                             br[jj >> 1][(jj & 1) * 2],
                             br[jj >> 1][(jj & 1) * 2 + 1]);
        }
        buf = (buf + 1 == NSTAGE) ? 0 : buf + 1;
    }

    const int ncol0 = n0 + wn * 32;
#pragma unroll
    for (int i = 0; i < 4; i++) {
        int row = m0 + wm * 64 + i * 16 + (lane >> 2);
        float* o0 = out + (size_t)row * V_DIM + ncol0;
        float* o1 = o0 + (size_t)8 * V_DIM;
#pragma unroll
        for (int jj = 0; jj < 4; jj++) {
            int col = jj * 8 + (lane & 3) * 2;
            float bx = __ldg(bias + ncol0 + col);
            float by = __ldg(bias + ncol0 + col + 1);
            float2 v0 = make_float2(acc[i][jj][0] + bx, acc[i][jj][1] + by);
            float2 v1 = make_float2(acc[i][jj][2] + bx, acc[i][jj][3] + by);
            *(float2*)(o0 + col) = v0;
            *(float2*)(o1 + col) = v1;
        }
    }
}

// ---------------------------------------------------------------------------
// launch
// ---------------------------------------------------------------------------
extern "C" void kernel_launch(void* const* d_in, const int* in_sizes, int n_in,
                              void* d_out, int out_size) {
    const int*   ids  = (const int*)d_in[0];
    const float* emb  = (const float*)d_in[1];
    const float* proj = (const float*)d_in[2];
    const float* bias = (const float*)d_in[3];
    float* out = (float*)d_out;

    cudaFuncSetAttribute(rin_fused_kernel,
                         cudaFuncAttributeMaxDynamicSharedMemorySize, SM_TOTAL);

    rin_conv_kernel<<<(V_DIM * K_DIM / 4 + 255) / 256, 256>>>(proj);
    rin_fused_kernel<<<NSCAN + NTILE_M * NTILE_N, 256, SM_TOTAL>>>(
        ids, emb, out, bias);
}

// round 8
// speedup vs baseline: 1.6044x; 1.1928x over previous
#include <cuda_runtime.h>
#include <cuda_fp16.h>
#include <cstdint>
#include <cstddef>

// ---------------------------------------------------------------------------
// Problem constants
// ---------------------------------------------------------------------------
#define B_DIM 4
#define S_DIM 2048
#define V_DIM 32000
#define K_DIM 512            // 2*D
#define D_DIM 256
#define M_DIM 8192           // B*S
#define LUT_N 4096

// exact-double constants rounded to f32
#define PHI_F   1.6180339887498949f          // (1+sqrt5)/2
#define CINV_F  651.8986469044033f           // 4096 / (2*pi)
#define GRID_F  0.0015339807878856412f       // (2*pi) / 4096

// GEMM tiling
#define TM 128
#define TN 128
#define KC 64                // k elements per stage = 128 bytes fp16
#define NKC 8                // 512 / 64
#define NSTAGE 3

#define NSCAN 32             // scan blocks (8 per batch)
#define NTILE_N (V_DIM / TN) // 250
#define NTILE_M (M_DIM / TM) // 64

// scratch (device globals allowed; runtime alloc is not)
static __device__ __align__(256) __half g_A[(size_t)M_DIM * K_DIM];
static __device__ __align__(256) __half g_B[(size_t)V_DIM * K_DIM];
static __device__ int g_prog[NSCAN];   // per-scan-block step progress

// ---------------------------------------------------------------------------
// PTX helpers (base-arch only: cp.async, ldmatrix, mma.sync)
// ---------------------------------------------------------------------------
__device__ __forceinline__ uint32_t smem_u32(const void* p) {
    return (uint32_t)__cvta_generic_to_shared(p);
}
__device__ __forceinline__ void cp_async16(uint32_t dst, const void* src) {
    asm volatile("cp.async.cg.shared.global [%0], [%1], 16;"
                 :: "r"(dst), "l"(src) : "memory");
}
#define CP_COMMIT() asm volatile("cp.async.commit_group;" ::: "memory")
#define CP_WAIT1()  asm volatile("cp.async.wait_group 1;" ::: "memory")

__device__ __forceinline__ void ldmatrix_x4(uint32_t* r, uint32_t addr) {
    asm volatile("ldmatrix.sync.aligned.m8n8.x4.shared.b16 {%0,%1,%2,%3}, [%4];"
                 : "=r"(r[0]), "=r"(r[1]), "=r"(r[2]), "=r"(r[3]) : "r"(addr));
}

__device__ __forceinline__ void mma16816(float* c, const uint32_t* a,
                                         uint32_t b0, uint32_t b1) {
    asm volatile(
        "mma.sync.aligned.m16n8k16.row.col.f32.f16.f16.f32 "
        "{%0,%1,%2,%3}, {%4,%5,%6,%7}, {%8,%9}, {%0,%1,%2,%3};"
        : "+f"(c[0]), "+f"(c[1]), "+f"(c[2]), "+f"(c[3])
        : "r"(a[0]), "r"(a[1]), "r"(a[2]), "r"(a[3]), "r"(b0), "r"(b1));
}

__device__ __forceinline__ uint32_t sw128(uint32_t off) {
    return off ^ ((off >> 3) & 0x70);
}

__device__ __forceinline__ int ld_acq(const int* p) {
    int v;
    asm volatile("ld.acquire.gpu.global.b32 %0, [%1];" : "=r"(v) : "l"(p));
    return v;
}
__device__ __forceinline__ void st_rel(int* p, int v) {
    asm volatile("st.release.gpu.global.b32 [%0], %1;" :: "l"(p), "r"(v) : "memory");
}

// Guard-free correctly-rounded fp32 division (Markstein). Valid for normal
// a, b with no overflow in intermediates — here |a|<=1, b in [1, ~3].
__device__ __forceinline__ float div_rn_fast(float a, float b) {
    float r;
    asm("rcp.approx.f32 %0, %1;" : "=f"(r) : "f"(b));
    float e = __fmaf_rn(-b, r, 1.0f);
    r = __fmaf_rn(r, e, r);
    e = __fmaf_rn(-b, r, 1.0f);
    r = __fmaf_rn(r, e, r);
    float q = __fmul_rn(a, r);
    float rem = __fmaf_rn(-b, q, a);
    return __fmaf_rn(rem, r, q);
}

// ---------------------------------------------------------------------------
// Kernel A: proj fp32 -> fp16, plus progress-flag reset (runs before fused)
// ---------------------------------------------------------------------------
__global__ void rin_conv_kernel(const float* __restrict__ p) {
    if (blockIdx.x == 0 && threadIdx.x < NSCAN) g_prog[threadIdx.x] = 0;
    size_t i = ((size_t)blockIdx.x * blockDim.x + threadIdx.x) * 4;
    if (i < (size_t)V_DIM * K_DIM) {
        float4 v = *(const float4*)(p + i);
        __half2 h0 = __floats2half2_rn(v.x, v.y);
        __half2 h1 = __floats2half2_rn(v.z, v.w);
        uint2 st;
        st.x = *(uint32_t*)&h0;
        st.y = *(uint32_t*)&h1;
        *(uint2*)(g_B + i) = st;
    }
}

// ---------------------------------------------------------------------------
// Fused kernel: bids 0..31 = scan producers, bids 32.. = GEMM consumers.
// GEMM tile order is step-major/batch-minor so consumption tracks production.
// ---------------------------------------------------------------------------
#define A_TILE  16384                 // 128 rows * 128B
#define B_TILE  16384
#define STAGE_SZ (A_TILE + B_TILE)    // 32768
#define SM_TOTAL (NSTAGE * STAGE_SZ)  // 98304 per CTA

#define PF 8

__device__ __forceinline__ void gemm_load_stage(uint32_t sb, int stage, int kc,
                                                int m0, int n0, int tid) {
    const __half* Ag = g_A + (size_t)m0 * K_DIM + kc * KC;
    const __half* Bg = g_B + (size_t)n0 * K_DIM + kc * KC;
    uint32_t abase = sb + stage * STAGE_SZ;
    uint32_t bbase = abase + A_TILE;
#pragma unroll
    for (int it = 0; it < 4; it++) {                // A: 1024 16B units
        int u = tid + it * 256;
        int r = u >> 3, c = u & 7;
        uint32_t off = (uint32_t)(r * 128 + c * 16);
        cp_async16(abase + sw128(off), Ag + (size_t)r * K_DIM + c * 8);
    }
#pragma unroll
    for (int it = 0; it < 4; it++) {                // B: 1024 16B units
        int u = tid + it * 256;
        int r = u >> 3, c = u & 7;
        uint32_t off = (uint32_t)(r * 128 + c * 16);
        cp_async16(bbase + sw128(off), Bg + (size_t)r * K_DIM + c * 8);
    }
    CP_COMMIT();
}

__global__ void __launch_bounds__(256, 2) rin_fused_kernel(
        const int* __restrict__ ids, const float* __restrict__ emb,
        float* __restrict__ out, const float* __restrict__ bias) {
    extern __shared__ char smem[];
    const int tid = threadIdx.x;

    if (blockIdx.x < NSCAN) {
        // ------------------------- scan producer -------------------------
        float* s_sin = (float*)smem;
        float* s_cos = s_sin + LUT_N;
        for (int i = tid; i < LUT_N; i += 256) {
            float g = __fmul_rn((float)i, GRID_F);
            s_sin[i] = sinf(g);
            s_cos[i] = cosf(g);
        }
        __syncthreads();
        if (tid >= 32) return;                 // only warp 0 runs chains

        const int bid = blockIdx.x;
        const int b = bid >> 3;
        const int d = ((bid & 7) << 5) + tid;

        const int* rid = ids + b * S_DIM;
        float hr = 0.0f, hi = 0.0f;

        float wp[PF], bp[PF];
#pragma unroll
        for (int j = 0; j < PF; j++) {
            int id = __ldg(rid + j);
            wp[j] = __ldg(emb + (size_t)id * K_DIM + d);
            bp[j] = __ldg(emb + (size_t)id * K_DIM + D_DIM + d);
        }

        __half* arow = g_A + (size_t)b * S_DIM * K_DIM + d;

        for (int s0 = 0; s0 < S_DIM; s0 += PF) {
#pragma unroll
            for (int j = 0; j < PF; j++) {
                int s = s0 + j;
                float w = wp[j];
                float bt = bp[j];
                if (s + PF < S_DIM) {
                    int id = __ldg(rid + s + PF);
                    wp[j] = __ldg(emb + (size_t)id * K_DIM + d);
                    bp[j] = __ldg(emb + (size_t)id * K_DIM + D_DIM + d);
                }
                float lam = __fadd_rn(1.0f, fabsf(w));
                float tp  = __fmul_rn((float)s, PHI_F);
                float tr  = __fadd_rn(__fadd_rn(div_rn_fast(hr, lam), bt), tp);
                float ti  = __fadd_rn(__fadd_rn(div_rn_fast(hi, lam), bt), tp);
                int ir = __float2int_rd(__fmul_rn(tr, CINV_F)) & (LUT_N - 1);
                int ii = __float2int_rd(__fmul_rn(ti, CINV_F)) & (LUT_N - 1);
                float sr = s_sin[ir], cr = s_cos[ir];
                float si = s_sin[ii], ci = s_cos[ii];
                float nhr = __fsub_rn(__fmul_rn(cr, ci), __fmul_rn(sr, si));
                float nhi = __fadd_rn(__fmul_rn(cr, si), __fmul_rn(sr, ci));
                hr = nhr;
                hi = nhi;
                arow[(size_t)s * K_DIM]         = __float2half_rn(nhr);
                arow[(size_t)s * K_DIM + D_DIM] = __float2half_rn(nhi);
            }
            if (((s0 + PF) & 127) == 0) {       // publish every 128 steps
                __threadfence();
                __syncwarp();
                if (tid == 0) st_rel(&g_prog[bid], s0 + PF);
            }
        }
        return;
    }

    // --------------------------- GEMM consumer ---------------------------
    uint32_t sb = smem_u32(smem);
    const int g = blockIdx.x - NSCAN;
    // step-major, batch-minor tile order: matches scan production order
    const int mt = g / NTILE_N;              // 0..63
    const int jj_step = mt >> 2;             // step group 0..15
    const int bb = mt & 3;                   // batch
    const int m0 = bb * S_DIM + jj_step * TM;
    const int n0 = (g % NTILE_N) * TN;
    const int lane = tid & 31;
    const int wid = tid >> 5;
    const int wm = wid & 1;
    const int wn = wid >> 1;

    // wait until this tile's 128 A-rows are produced by all 8 scan blocks of bb
    {
        const int s_end = jj_step * TM + TM;
        if (tid < 8) {
            const int* fp = &g_prog[bb * 8 + tid];
            while (ld_acq(fp) < s_end) __nanosleep(128);
        }
        __syncthreads();
    }

    float acc[4][4][4];
#pragma unroll
    for (int i = 0; i < 4; i++)
#pragma unroll
        for (int j = 0; j < 4; j++)
#pragma unroll
            for (int k = 0; k < 4; k++) acc[i][j][k] = 0.0f;

    gemm_load_stage(sb, 0, 0, m0, n0, tid);
    gemm_load_stage(sb, 1, 1, m0, n0, tid);

    const int a_row  = wm * 64 + (lane & 15);
    const int a_sega = (lane >> 4) * 16;
    const int b_row  = wn * 32 + (lane & 7) + ((lane >> 4) << 3);
    const int b_sega = ((lane >> 3) & 1) * 16;

    int buf = 0;
    for (int kc = 0; kc < NKC; kc++) {
        CP_WAIT1();
        __syncthreads();
        if (kc + 2 < NKC)
            gemm_load_stage(sb, (buf + 2 >= NSTAGE) ? buf + 2 - NSTAGE : buf + 2,
                            kc + 2, m0, n0, tid);

        const uint32_t abase = sb + buf * STAGE_SZ;
        const uint32_t bbase = abase + A_TILE;
#pragma unroll
        for (int ks = 0; ks < 4; ks++) {
            uint32_t ar[4][4];
#pragma unroll
            for (int i = 0; i < 4; i++) {
                uint32_t off = (uint32_t)((a_row + i * 16) * 128 + ks * 32 + a_sega);
                ldmatrix_x4(ar[i], abase + sw128(off));
            }
            uint32_t br[2][4];
#pragma unroll
            for (int j = 0; j < 2; j++) {
                uint32_t off = (uint32_t)((b_row + j * 16) * 128 + ks * 32 + b_sega);
                ldmatrix_x4(br[j], bbase + sw128(off));
            }
#pragma unroll
            for (int i = 0; i < 4; i++)
#pragma unroll
                for (int j2 = 0; j2 < 4; j2++)
                    mma16816(acc[i][j2], ar[i],
                             br[j2 >> 1][(j2 & 1) * 2],
                             br[j2 >> 1][(j2 & 1) * 2 + 1]);
        }
        buf = (buf + 1 == NSTAGE) ? 0 : buf + 1;
    }

    const int ncol0 = n0 + wn * 32;
#pragma unroll
    for (int i = 0; i < 4; i++) {
        int row = m0 + wm * 64 + i * 16 + (lane >> 2);
        float* o0 = out + (size_t)row * V_DIM + ncol0;
        float* o1 = o0 + (size_t)8 * V_DIM;
#pragma unroll
        for (int j2 = 0; j2 < 4; j2++) {
            int col = j2 * 8 + (lane & 3) * 2;
            float bx = __ldg(bias + ncol0 + col);
            float by = __ldg(bias + ncol0 + col + 1);
            float2 v0 = make_float2(acc[i][j2][0] + bx, acc[i][j2][1] + by);
            float2 v1 = make_float2(acc[i][j2][2] + bx, acc[i][j2][3] + by);
            *(float2*)(o0 + col) = v0;
            *(float2*)(o1 + col) = v1;
        }
    }
}

// ---------------------------------------------------------------------------
// launch
// ---------------------------------------------------------------------------
extern "C" void kernel_launch(void* const* d_in, const int* in_sizes, int n_in,
                              void* d_out, int out_size) {
    const int*   ids  = (const int*)d_in[0];
    const float* emb  = (const float*)d_in[1];
    const float* proj = (const float*)d_in[2];
    const float* bias = (const float*)d_in[3];
    float* out = (float*)d_out;

    cudaFuncSetAttribute(rin_fused_kernel,
                         cudaFuncAttributeMaxDynamicSharedMemorySize, SM_TOTAL);

    rin_conv_kernel<<<(V_DIM * K_DIM / 4 + 255) / 256, 256>>>(proj);
    rin_fused_kernel<<<NSCAN + NTILE_M * NTILE_N, 256, SM_TOTAL>>>(
        ids, emb, out, bias);
}